// round 2
// baseline (speedup 1.0000x reference)
#include <cuda_runtime.h>
#include <math.h>

#define S_LEN 2048
#define HID   4096
#define NQH   32
#define NKVH  8
#define HD    128
#define QKV_N 6144
#define KV_OFF 4096
#define V_OFF  5120
#define Q_SIZE 4096

// Scratch (device globals: allocation-free per harness rules)
__device__ float g_xn[S_LEN * HID];       // 32 MB
__device__ float g_qkv[S_LEN * QKV_N];    // 48 MB
__device__ float g_attn[S_LEN * Q_SIZE];  // 32 MB

// ---------------------------------------------------------------------------
// RMSNorm: one block per row, 256 threads, float4
// ---------------------------------------------------------------------------
__global__ __launch_bounds__(256) void rmsnorm_kernel(const float* __restrict__ x,
                                                      const float* __restrict__ w) {
    int row = blockIdx.x;
    int t = threadIdx.x;
    const float4* xr = (const float4*)(x + (size_t)row * HID);
    float4 v[4];
    float ss = 0.f;
#pragma unroll
    for (int i = 0; i < 4; i++) {
        v[i] = xr[t + i * 256];
        ss += v[i].x * v[i].x + v[i].y * v[i].y + v[i].z * v[i].z + v[i].w * v[i].w;
    }
    __shared__ float red[8];
#pragma unroll
    for (int o = 16; o > 0; o >>= 1) ss += __shfl_xor_sync(0xffffffffu, ss, o);
    if ((t & 31) == 0) red[t >> 5] = ss;
    __syncthreads();
    if (t < 8) {
        float s2 = red[t];
#pragma unroll
        for (int o = 4; o > 0; o >>= 1) s2 += __shfl_xor_sync(0xffu, s2, o);
        if (t == 0) red[0] = s2;
    }
    __syncthreads();
    float inv = rsqrtf(red[0] / (float)HID + 1e-5f);
    const float4* wr = (const float4*)w;
    float4* o = (float4*)(g_xn + (size_t)row * HID);
#pragma unroll
    for (int i = 0; i < 4; i++) {
        float4 wv = wr[t + i * 256];
        float4 ov;
        ov.x = v[i].x * inv * wv.x;
        ov.y = v[i].y * inv * wv.y;
        ov.z = v[i].z * inv * wv.z;
        ov.w = v[i].w * inv * wv.w;
        o[t + i * 256] = ov;
    }
}

// ---------------------------------------------------------------------------
// SGEMM  C[m][n] = sum_k A[m][k] * B[n][k]   (both row-major, K contiguous)
// 128x128 tile, BK=8, 256 threads, 8x8 per thread
// ---------------------------------------------------------------------------
__global__ __launch_bounds__(256, 2) void sgemm_nt_kernel(const float* __restrict__ A,
                                                          const float* __restrict__ B,
                                                          float* __restrict__ C,
                                                          int M, int N, int K) {
    __shared__ float As[8][128];
    __shared__ float Bs[8][128];
    int t = threadIdx.x;
    int tx = t & 15, ty = t >> 4;
    int m0 = blockIdx.y * 128, n0 = blockIdx.x * 128;
    const float* Ab = A + (size_t)m0 * K;
    const float* Bb = B + (size_t)n0 * K;
    int lrow = t >> 1;
    int lk = (t & 1) * 4;
    float acc[8][8];
#pragma unroll
    for (int i = 0; i < 8; i++)
#pragma unroll
        for (int j = 0; j < 8; j++) acc[i][j] = 0.f;

    for (int k0 = 0; k0 < K; k0 += 8) {
        float4 av = *(const float4*)(Ab + (size_t)lrow * K + k0 + lk);
        float4 bv = *(const float4*)(Bb + (size_t)lrow * K + k0 + lk);
        __syncthreads();
        As[lk + 0][lrow] = av.x; As[lk + 1][lrow] = av.y;
        As[lk + 2][lrow] = av.z; As[lk + 3][lrow] = av.w;
        Bs[lk + 0][lrow] = bv.x; Bs[lk + 1][lrow] = bv.y;
        Bs[lk + 2][lrow] = bv.z; Bs[lk + 3][lrow] = bv.w;
        __syncthreads();
#pragma unroll
        for (int k = 0; k < 8; k++) {
            float a[8], b[8];
            *(float4*)(a)     = *(const float4*)&As[k][ty * 8];
            *(float4*)(a + 4) = *(const float4*)&As[k][ty * 8 + 4];
            *(float4*)(b)     = *(const float4*)&Bs[k][tx * 8];
            *(float4*)(b + 4) = *(const float4*)&Bs[k][tx * 8 + 4];
#pragma unroll
            for (int i = 0; i < 8; i++)
#pragma unroll
                for (int j = 0; j < 8; j++)
                    acc[i][j] = fmaf(a[i], b[j], acc[i][j]);
        }
    }
    float* Cb = C + (size_t)(m0 + ty * 8) * N + n0 + tx * 8;
#pragma unroll
    for (int i = 0; i < 8; i++) {
        *(float4*)(Cb + (size_t)i * N)     = make_float4(acc[i][0], acc[i][1], acc[i][2], acc[i][3]);
        *(float4*)(Cb + (size_t)i * N + 4) = make_float4(acc[i][4], acc[i][5], acc[i][6], acc[i][7]);
    }
}

// ---------------------------------------------------------------------------
// RoPE applied in-place to Q (heads 0..31) and K (heads 32..39) in g_qkv
// ---------------------------------------------------------------------------
__global__ __launch_bounds__(64) void rope_kernel(const int* __restrict__ positions) {
    int s = blockIdx.x;
    int h = blockIdx.y;  // 0..39
    int d = threadIdx.x; // 0..63
    float pos = (float)positions[s];
    float invf = powf(10000.0f, -((float)(2 * d)) / 128.0f);
    float f = pos * invf;
    float c = cosf(f), sn = sinf(f);
    float* base;
    if (h < NQH) base = g_qkv + (size_t)s * QKV_N + h * HD;
    else         base = g_qkv + (size_t)s * QKV_N + KV_OFF + (h - NQH) * HD;
    float x1 = base[d];
    float x2 = base[d + 64];
    base[d]      = x1 * c - x2 * sn;
    base[d + 64] = x2 * c + x1 * sn;
}

// ---------------------------------------------------------------------------
// Flash attention (causal, GQA 4:1). 64 q-rows x 64 kv-rows tiles, d=128.
// 256 threads. Dynamic smem ~113 KB.
// ---------------------------------------------------------------------------
__global__ __launch_bounds__(256) void flash_kernel() {
    extern __shared__ float sm[];
    float* sQ  = sm;                   // 64*128
    float* sKt = sQ + 64 * 128;        // 128*65 (d-major, pad 65)
    float* sV  = sKt + 128 * 65;       // 64*128
    float* sS  = sV + 64 * 128;        // 64*64
    float* sM  = sS + 64 * 64;         // 64
    float* sL  = sM + 64;              // 64
    float* sC  = sL + 64;              // 64

    int qt = blockIdx.x;    // q tile 0..31
    int h  = blockIdx.y;    // head 0..31
    int kvh = h >> 2;
    int t = threadIdx.x;
    int tx = t & 15, ty = t >> 4;
    int q0 = qt * 64;

    // load Q tile
    {
        const float* gq = g_qkv + (size_t)q0 * QKV_N + h * HD;
#pragma unroll
        for (int i = 0; i < 8; i++) {
            int idx = t + i * 256;
            int r = idx >> 5, c4 = idx & 31;
            *(float4*)(sQ + r * 128 + c4 * 4) = *(const float4*)(gq + (size_t)r * QKV_N + c4 * 4);
        }
    }
    if (t < 64) { sM[t] = -3e38f; sL[t] = 0.f; }

    float acc[4][8];
#pragma unroll
    for (int i = 0; i < 4; i++)
#pragma unroll
        for (int j = 0; j < 8; j++) acc[i][j] = 0.f;

    const float scale = 0.08838834764831845f; // 1/sqrt(128)

    for (int kt = 0; kt <= qt; kt++) {
        int n0 = kt * 64;
        __syncthreads();
        // load K (transposed) and V tiles
        const float* gk = g_qkv + (size_t)n0 * QKV_N + KV_OFF + kvh * HD;
        const float* gv = g_qkv + (size_t)n0 * QKV_N + V_OFF + kvh * HD;
#pragma unroll
        for (int i = 0; i < 8; i++) {
            int idx = t + i * 256;
            int r = idx >> 5, c4 = idx & 31;
            float4 k4 = *(const float4*)(gk + (size_t)r * QKV_N + c4 * 4);
            sKt[(c4 * 4 + 0) * 65 + r] = k4.x;
            sKt[(c4 * 4 + 1) * 65 + r] = k4.y;
            sKt[(c4 * 4 + 2) * 65 + r] = k4.z;
            sKt[(c4 * 4 + 3) * 65 + r] = k4.w;
            *(float4*)(sV + r * 128 + c4 * 4) = *(const float4*)(gv + (size_t)r * QKV_N + c4 * 4);
        }
        __syncthreads();

        // S = Q K^T (64x64), thread computes 4x4
        float sv[4][4];
#pragma unroll
        for (int i = 0; i < 4; i++)
#pragma unroll
            for (int j = 0; j < 4; j++) sv[i][j] = 0.f;
        for (int d = 0; d < 128; d++) {
            float qv[4], kv[4];
#pragma unroll
            for (int i = 0; i < 4; i++) qv[i] = sQ[(ty * 4 + i) * 128 + d];
#pragma unroll
            for (int j = 0; j < 4; j++) kv[j] = sKt[d * 65 + tx * 4 + j];
#pragma unroll
            for (int i = 0; i < 4; i++)
#pragma unroll
                for (int j = 0; j < 4; j++)
                    sv[i][j] = fmaf(qv[i], kv[j], sv[i][j]);
        }
#pragma unroll
        for (int i = 0; i < 4; i++) {
            int r = ty * 4 + i;
            float4 st;
            float vv[4];
#pragma unroll
            for (int j = 0; j < 4; j++) {
                float val = sv[i][j] * scale;
                if (kt == qt && (tx * 4 + j) > r) val = -3e38f;
                vv[j] = val;
            }
            st.x = vv[0]; st.y = vv[1]; st.z = vv[2]; st.w = vv[3];
            *(float4*)(sS + r * 64 + tx * 4) = st;
        }
        __syncthreads();

        // online softmax: warp w owns rows w*8 .. w*8+7
        {
            int w = t >> 5, lane = t & 31;
            for (int rr = 0; rr < 8; rr++) {
                int r = w * 8 + rr;
                float v0 = sS[r * 64 + lane];
                float v1 = sS[r * 64 + lane + 32];
                float mx = fmaxf(v0, v1);
#pragma unroll
                for (int o = 16; o > 0; o >>= 1) mx = fmaxf(mx, __shfl_xor_sync(0xffffffffu, mx, o));
                float mold = sM[r];
                float mnew = fmaxf(mold, mx);
                float p0 = __expf(v0 - mnew);
                float p1 = __expf(v1 - mnew);
                float psum = p0 + p1;
#pragma unroll
                for (int o = 16; o > 0; o >>= 1) psum += __shfl_xor_sync(0xffffffffu, psum, o);
                sS[r * 64 + lane] = p0;
                sS[r * 64 + lane + 32] = p1;
                if (lane == 0) {
                    float corr = __expf(mold - mnew);
                    sC[r] = corr;
                    sL[r] = sL[r] * corr + psum;
                    sM[r] = mnew;
                }
            }
        }
        __syncthreads();

        // rescale accumulator, add P @ V (thread: 4 rows x 8 cols)
        float corr_i[4];
#pragma unroll
        for (int i = 0; i < 4; i++) corr_i[i] = sC[ty * 4 + i];
#pragma unroll
        for (int i = 0; i < 4; i++)
#pragma unroll
            for (int j = 0; j < 8; j++) acc[i][j] *= corr_i[i];
        for (int n = 0; n < 64; n++) {
            float p[4];
#pragma unroll
            for (int i = 0; i < 4; i++) p[i] = sS[(ty * 4 + i) * 64 + n];
            float4 va = *(const float4*)(sV + n * 128 + tx * 8);
            float4 vb = *(const float4*)(sV + n * 128 + tx * 8 + 4);
#pragma unroll
            for (int i = 0; i < 4; i++) {
                acc[i][0] = fmaf(p[i], va.x, acc[i][0]);
                acc[i][1] = fmaf(p[i], va.y, acc[i][1]);
                acc[i][2] = fmaf(p[i], va.z, acc[i][2]);
                acc[i][3] = fmaf(p[i], va.w, acc[i][3]);
                acc[i][4] = fmaf(p[i], vb.x, acc[i][4]);
                acc[i][5] = fmaf(p[i], vb.y, acc[i][5]);
                acc[i][6] = fmaf(p[i], vb.z, acc[i][6]);
                acc[i][7] = fmaf(p[i], vb.w, acc[i][7]);
            }
        }
    }
    __syncthreads();

    // write: out row = q0+r, col = h*128 + tx*8 + j
    float* go = g_attn + (size_t)q0 * Q_SIZE + h * HD;
#pragma unroll
    for (int i = 0; i < 4; i++) {
        int r = ty * 4 + i;
        float linv = 1.0f / sL[r];
        float4 oa = make_float4(acc[i][0] * linv, acc[i][1] * linv, acc[i][2] * linv, acc[i][3] * linv);
        float4 ob = make_float4(acc[i][4] * linv, acc[i][5] * linv, acc[i][6] * linv, acc[i][7] * linv);
        *(float4*)(go + (size_t)r * Q_SIZE + tx * 8)     = oa;
        *(float4*)(go + (size_t)r * Q_SIZE + tx * 8 + 4) = ob;
    }
}

// ---------------------------------------------------------------------------
extern "C" void kernel_launch(void* const* d_in, const int* in_sizes, int n_in,
                              void* d_out, int out_size) {
    const int*   positions = (const int*)d_in[0];
    const float* hidden    = (const float*)d_in[1];
    const float* lnw       = (const float*)d_in[2];
    const float* w_qkv     = (const float*)d_in[3];
    const float* w_o       = (const float*)d_in[4];
    float* out = (float*)d_out;

    void* p;
    cudaGetSymbolAddress(&p, g_xn);   float* xn   = (float*)p;
    cudaGetSymbolAddress(&p, g_qkv);  float* qkv  = (float*)p;
    cudaGetSymbolAddress(&p, g_attn); float* attn = (float*)p;

    int flash_smem = (64 * 128 + 128 * 65 + 64 * 128 + 64 * 64 + 3 * 64) * sizeof(float);
    cudaFuncSetAttribute(flash_kernel, cudaFuncAttributeMaxDynamicSharedMemorySize, flash_smem);

    // 1. RMSNorm
    rmsnorm_kernel<<<S_LEN, 256>>>(hidden, lnw);

    // 2. QKV projection: [2048,6144] = xn @ w_qkv^T
    {
        dim3 grid(QKV_N / 128, S_LEN / 128);
        sgemm_nt_kernel<<<grid, 256>>>(xn, w_qkv, qkv, S_LEN, QKV_N, HID);
    }

    // 3. RoPE on Q and K in place
    {
        dim3 grid(S_LEN, NQH + NKVH);
        rope_kernel<<<grid, 64>>>(positions);
    }

    // 4. Flash attention -> g_attn [2048, 4096]
    {
        dim3 grid(S_LEN / 64, NQH);
        flash_kernel<<<grid, 256, flash_smem>>>();
    }

    // 5. Output projection: [2048,4096] = attn @ w_o^T -> d_out
    {
        dim3 grid(Q_SIZE / 128, S_LEN / 128);
        sgemm_nt_kernel<<<grid, 256>>>(attn, w_o, out, S_LEN, Q_SIZE, HID);
    }
    (void)in_sizes; (void)n_in; (void)out_size;
}

// round 6
// speedup vs baseline: 1.8579x; 1.8579x over previous
#include <cuda_runtime.h>
#include <cuda_bf16.h>
#include <math.h>
#include <stdint.h>

#define S_LEN 2048
#define HID   4096
#define NQH   32
#define NKVH  8
#define HD    128
#define QKV_N 6144
#define KV_OFF 4096
#define V_OFF  5120
#define Q_SIZE 4096

// ---------------- scratch (device globals, allocation-free) ----------------
__device__ float         g_qkv[S_LEN * QKV_N];
__device__ __nv_bfloat16 g_xn_hi[S_LEN * HID];
__device__ __nv_bfloat16 g_xn_mid[S_LEN * HID];
__device__ __nv_bfloat16 g_wqkv_hi[QKV_N * HID];
__device__ __nv_bfloat16 g_wqkv_mid[QKV_N * HID];
__device__ __nv_bfloat16 g_wo_hi[Q_SIZE * HID];
__device__ __nv_bfloat16 g_wo_mid[Q_SIZE * HID];
__device__ __nv_bfloat16 g_attn_hi[S_LEN * Q_SIZE];
__device__ __nv_bfloat16 g_attn_mid[S_LEN * Q_SIZE];

// ---------------- helpers ----------------
__device__ __forceinline__ uint32_t smem_u32(const void* p) {
    uint32_t a;
    asm("{ .reg .u64 t; cvta.to.shared.u64 t, %1; cvt.u32.u64 %0, t; }" : "=r"(a) : "l"(p));
    return a;
}
__device__ __forceinline__ void cp_async16(uint32_t dst, const void* src) {
    asm volatile("cp.async.cg.shared.global [%0], [%1], 16;" :: "r"(dst), "l"(src) : "memory");
}
__device__ __forceinline__ void cp_commit() { asm volatile("cp.async.commit_group;" ::: "memory"); }
__device__ __forceinline__ void cp_wait1() { asm volatile("cp.async.wait_group 1;" ::: "memory"); }
__device__ __forceinline__ void cp_wait0() { asm volatile("cp.async.wait_group 0;" ::: "memory"); }

#define LDSM4(r, addr)                                                             \
    asm volatile("ldmatrix.sync.aligned.m8n8.x4.shared.b16 {%0,%1,%2,%3}, [%4];"   \
        : "=r"((r)[0]), "=r"((r)[1]), "=r"((r)[2]), "=r"((r)[3]) : "r"(addr))

#define MMA16816(d, a, b0, b1)                                                     \
    asm volatile("mma.sync.aligned.m16n8k16.row.col.f32.bf16.bf16.f32 "            \
        "{%0,%1,%2,%3}, {%4,%5,%6,%7}, {%8,%9}, {%0,%1,%2,%3};"                    \
        : "+f"((d)[0]), "+f"((d)[1]), "+f"((d)[2]), "+f"((d)[3])                   \
        : "r"((a)[0]), "r"((a)[1]), "r"((a)[2]), "r"((a)[3]), "r"(b0), "r"(b1))

// ---------------------------------------------------------------------------
// RMSNorm -> split bf16 (hi, mid)
// ---------------------------------------------------------------------------
__global__ __launch_bounds__(256) void rmsnorm_kernel(const float* __restrict__ x,
                                                      const float* __restrict__ w) {
    int row = blockIdx.x;
    int t = threadIdx.x;
    const float4* xr = (const float4*)(x + (size_t)row * HID);
    float4 v[4];
    float ss = 0.f;
#pragma unroll
    for (int i = 0; i < 4; i++) {
        v[i] = xr[t + i * 256];
        ss += v[i].x * v[i].x + v[i].y * v[i].y + v[i].z * v[i].z + v[i].w * v[i].w;
    }
    __shared__ float red[8];
#pragma unroll
    for (int o = 16; o > 0; o >>= 1) ss += __shfl_xor_sync(0xffffffffu, ss, o);
    if ((t & 31) == 0) red[t >> 5] = ss;
    __syncthreads();
    if (t < 8) {
        float s2 = red[t];
#pragma unroll
        for (int o = 4; o > 0; o >>= 1) s2 += __shfl_xor_sync(0xffu, s2, o);
        if (t == 0) red[0] = s2;
    }
    __syncthreads();
    float inv = rsqrtf(red[0] / (float)HID + 1e-5f);
    const float4* wr = (const float4*)w;
    __nv_bfloat16* oh = g_xn_hi + (size_t)row * HID;
    __nv_bfloat16* om = g_xn_mid + (size_t)row * HID;
#pragma unroll
    for (int i = 0; i < 4; i++) {
        float4 wv = wr[t + i * 256];
        float f[4];
        f[0] = v[i].x * inv * wv.x; f[1] = v[i].y * inv * wv.y;
        f[2] = v[i].z * inv * wv.z; f[3] = v[i].w * inv * wv.w;
        int base = (t + i * 256) * 4;
        __nv_bfloat162 h2[2], m2[2];
#pragma unroll
        for (int j = 0; j < 2; j++) {
            __nv_bfloat16 h0 = __float2bfloat16(f[2*j]);
            __nv_bfloat16 h1 = __float2bfloat16(f[2*j+1]);
            h2[j].x = h0; h2[j].y = h1;
            m2[j].x = __float2bfloat16(f[2*j]   - __bfloat162float(h0));
            m2[j].y = __float2bfloat16(f[2*j+1] - __bfloat162float(h1));
        }
        *(__nv_bfloat162*)(oh + base)     = h2[0];
        *(__nv_bfloat162*)(oh + base + 2) = h2[1];
        *(__nv_bfloat162*)(om + base)     = m2[0];
        *(__nv_bfloat162*)(om + base + 2) = m2[1];
    }
}

// ---------------------------------------------------------------------------
// fp32 -> (hi, mid) bf16 split
// ---------------------------------------------------------------------------
__global__ __launch_bounds__(256) void split_kernel(const float* __restrict__ s,
                                                    __nv_bfloat16* __restrict__ hi,
                                                    __nv_bfloat16* __restrict__ mid, int n4) {
    int i = blockIdx.x * 256 + threadIdx.x;
    if (i >= n4) return;
    float4 v = ((const float4*)s)[i];
    float f[4] = {v.x, v.y, v.z, v.w};
    __nv_bfloat162 h2[2], m2[2];
#pragma unroll
    for (int j = 0; j < 2; j++) {
        __nv_bfloat16 h0 = __float2bfloat16(f[2*j]);
        __nv_bfloat16 h1 = __float2bfloat16(f[2*j+1]);
        h2[j].x = h0; h2[j].y = h1;
        m2[j].x = __float2bfloat16(f[2*j]   - __bfloat162float(h0));
        m2[j].y = __float2bfloat16(f[2*j+1] - __bfloat162float(h1));
    }
    *(__nv_bfloat162*)(hi + i*4)      = h2[0];
    *(__nv_bfloat162*)(hi + i*4 + 2)  = h2[1];
    *(__nv_bfloat162*)(mid + i*4)     = m2[0];
    *(__nv_bfloat162*)(mid + i*4 + 2) = m2[1];
}

// ---------------------------------------------------------------------------
// mma.sync bf16-split GEMM:  C[m][n] = sum_k A[m][k]*B[n][k]   (fp32 accuracy)
// 128x128 tile, BK=32, 8 warps (4x2), warp tile 32x64, 2-stage cp.async.
// smem row stride 80B (conflict-free ldmatrix).
// ---------------------------------------------------------------------------
#define GK   32
#define TSTR 80                       // bytes per smem row (32 bf16 + pad)
#define TILE_B (128 * TSTR)           // 10240 B per matrix tile
#define STAGE_B (4 * TILE_B)          // 40960 B per stage
#define GEMM_SMEM (2 * STAGE_B)       // 81920 B

__global__ __launch_bounds__(256) void gemm_mma_kernel(
    const __nv_bfloat16* __restrict__ Ah, const __nv_bfloat16* __restrict__ Am,
    const __nv_bfloat16* __restrict__ Bh, const __nv_bfloat16* __restrict__ Bm,
    float* __restrict__ C, int K, int N)
{
    extern __shared__ char smem[];
    int t = threadIdx.x;
    int lane = t & 31, warp = t >> 5;
    int wm = warp & 3, wn = warp >> 2;           // 4 x 2 warp grid
    int m0 = blockIdx.y * 128, n0 = blockIdx.x * 128;

    const __nv_bfloat16* gsrc[4] = { Ah + (size_t)m0 * K, Am + (size_t)m0 * K,
                                     Bh + (size_t)n0 * K, Bm + (size_t)n0 * K };
    uint32_t sbase = smem_u32(smem);

    // load mapping: per tile 512 16B chunks; thread does rows (t>>2) and (t>>2)+64, seg t&3
    int lr = t >> 2, lseg = t & 3;

    float acc[2][8][4];
#pragma unroll
    for (int i = 0; i < 2; i++)
#pragma unroll
        for (int j = 0; j < 8; j++)
#pragma unroll
            for (int q = 0; q < 4; q++) acc[i][j][q] = 0.f;

    int NC = K / GK;

    // prologue: stage 0
    {
#pragma unroll
        for (int mt = 0; mt < 4; mt++) {
            const __nv_bfloat16* g = gsrc[mt] + (size_t)lr * K + lseg * 8;
            uint32_t d = sbase + mt * TILE_B + lr * TSTR + lseg * 16;
            cp_async16(d, g);
            cp_async16(d + 64 * TSTR, g + (size_t)64 * K);
        }
        cp_commit();
    }

    for (int c = 0; c < NC; c++) {
        int s = c & 1;
        if (c + 1 < NC) {
            int kc = (c + 1) * GK;
#pragma unroll
            for (int mt = 0; mt < 4; mt++) {
                const __nv_bfloat16* g = gsrc[mt] + (size_t)lr * K + kc + lseg * 8;
                uint32_t d = sbase + (s ^ 1) * STAGE_B + mt * TILE_B + lr * TSTR + lseg * 16;
                cp_async16(d, g);
                cp_async16(d + 64 * TSTR, g + (size_t)64 * K);
            }
            cp_commit();
            cp_wait1();
        } else {
            cp_wait0();
        }
        __syncthreads();

        uint32_t st = sbase + s * STAGE_B;
#pragma unroll
        for (int kk = 0; kk < 2; kk++) {
            // A fragments (hi, mid): m = wm*32 + mf*16 + (lane&15), kbyte = kk*32 + (lane>>4)*16
            uint32_t a_hi[2][4], a_mi[2][4];
            int kbA = kk * 32 + ((lane >> 4) << 4);
#pragma unroll
            for (int mf = 0; mf < 2; mf++) {
                uint32_t addr = st + (uint32_t)(wm * 32 + mf * 16 + (lane & 15)) * TSTR + kbA;
                LDSM4(a_hi[mf], addr);
                LDSM4(a_mi[mf], addr + TILE_B);
            }
            // B fragments (hi, mid): 4 groups of n16
            uint32_t b_hi[4][4], b_mi[4][4];
            int q = lane >> 3;
            int nbase = wn * 64 + ((q & 2) << 2) + (lane & 7);
            int kbB = kk * 32 + ((q & 1) << 4);
#pragma unroll
            for (int g = 0; g < 4; g++) {
                uint32_t addr = st + 2 * TILE_B + (uint32_t)(nbase + g * 16) * TSTR + kbB;
                LDSM4(b_hi[g], addr);
                LDSM4(b_mi[g], addr + TILE_B);
            }
            // 3-product split MMA
#pragma unroll
            for (int mf = 0; mf < 2; mf++) {
#pragma unroll
                for (int nf = 0; nf < 8; nf++) {
                    int g = nf >> 1, j = (nf & 1) * 2;
                    MMA16816(acc[mf][nf], a_hi[mf], b_hi[g][j], b_hi[g][j + 1]);
                    MMA16816(acc[mf][nf], a_hi[mf], b_mi[g][j], b_mi[g][j + 1]);
                    MMA16816(acc[mf][nf], a_mi[mf], b_hi[g][j], b_hi[g][j + 1]);
                }
            }
        }
        __syncthreads();
    }

    // epilogue: fp32 direct to global
#pragma unroll
    for (int mf = 0; mf < 2; mf++) {
#pragma unroll
        for (int nf = 0; nf < 8; nf++) {
            int r = m0 + wm * 32 + mf * 16 + (lane >> 2);
            int cc = n0 + wn * 64 + nf * 8 + (lane & 3) * 2;
            *(float2*)&C[(size_t)r * N + cc]       = make_float2(acc[mf][nf][0], acc[mf][nf][1]);
            *(float2*)&C[(size_t)(r + 8) * N + cc] = make_float2(acc[mf][nf][2], acc[mf][nf][3]);
        }
    }
}

// ---------------------------------------------------------------------------
// RoPE in-place on Q/K in g_qkv (fp32)
// ---------------------------------------------------------------------------
__global__ __launch_bounds__(64) void rope_kernel(const int* __restrict__ positions) {
    int s = blockIdx.x;
    int h = blockIdx.y;
    int d = threadIdx.x;
    float pos = (float)positions[s];
    float invf = powf(10000.0f, -((float)(2 * d)) / 128.0f);
    float f = pos * invf;
    float c = cosf(f), sn = sinf(f);
    float* base;
    if (h < NQH) base = g_qkv + (size_t)s * QKV_N + h * HD;
    else         base = g_qkv + (size_t)s * QKV_N + KV_OFF + (h - NQH) * HD;
    float x1 = base[d];
    float x2 = base[d + 64];
    base[d]      = x1 * c - x2 * sn;
    base[d + 64] = x2 * c + x1 * sn;
}

// ---------------------------------------------------------------------------
// Flash attention (causal, GQA). 64x64 tiles, d=128, fp32 math.
// K^T tile 16B-chunk XOR-swizzled -> conflict-free float4 LDS.
// Epilogue writes (hi, mid) bf16 split for the O-proj MMA GEMM.
// ---------------------------------------------------------------------------
__global__ __launch_bounds__(256) void flash_kernel() {
    extern __shared__ float sm[];
    float* sQ  = sm;                   // 64*128
    float* sKt = sQ + 64 * 128;        // 128 x 64, chunk-swizzled
    float* sV  = sKt + 128 * 64;       // 64*128
    float* sS  = sV + 64 * 128;        // 64*64
    float* sM  = sS + 64 * 64;         // 64
    float* sL  = sM + 64;              // 64
    float* sC  = sL + 64;              // 64

    int qt = blockIdx.x;
    int h  = blockIdx.y;
    int kvh = h >> 2;
    int t = threadIdx.x;
    int tx = t & 15, ty = t >> 4;
    int q0 = qt * 64;

    {
        const float* gq = g_qkv + (size_t)q0 * QKV_N + h * HD;
#pragma unroll
        for (int i = 0; i < 8; i++) {
            int idx = t + i * 256;
            int r = idx >> 5, c4 = idx & 31;
            *(float4*)(sQ + r * 128 + c4 * 4) = *(const float4*)(gq + (size_t)r * QKV_N + c4 * 4);
        }
    }
    if (t < 64) { sM[t] = -3e38f; sL[t] = 0.f; }

    float acc[4][8];
#pragma unroll
    for (int i = 0; i < 4; i++)
#pragma unroll
        for (int j = 0; j < 8; j++) acc[i][j] = 0.f;

    const float scale = 0.08838834764831845f;

    for (int kt = 0; kt <= qt; kt++) {
        int n0 = kt * 64;
        __syncthreads();
        const float* gk = g_qkv + (size_t)n0 * QKV_N + KV_OFF + kvh * HD;
        const float* gv = g_qkv + (size_t)n0 * QKV_N + V_OFF + kvh * HD;
#pragma unroll
        for (int i = 0; i < 8; i++) {
            int idx = t + i * 256;
            int r = idx >> 5, c4 = idx & 31;
            float4 k4 = *(const float4*)(gk + (size_t)r * QKV_N + c4 * 4);
            float kf[4] = {k4.x, k4.y, k4.z, k4.w};
#pragma unroll
            for (int q = 0; q < 4; q++) {
                int d = c4 * 4 + q;
                sKt[d * 64 + (((r >> 2) ^ (d & 15)) << 2) + (r & 3)] = kf[q];
            }
            *(float4*)(sV + r * 128 + c4 * 4) = *(const float4*)(gv + (size_t)r * QKV_N + c4 * 4);
        }
        __syncthreads();

        float sv[4][4];
#pragma unroll
        for (int i = 0; i < 4; i++)
#pragma unroll
            for (int j = 0; j < 4; j++) sv[i][j] = 0.f;
        for (int d0 = 0; d0 < 128; d0 += 4) {
            float4 q4[4];
#pragma unroll
            for (int i = 0; i < 4; i++)
                q4[i] = *(const float4*)(sQ + (ty * 4 + i) * 128 + d0);
#pragma unroll
            for (int dd = 0; dd < 4; dd++) {
                int d = d0 + dd;
                float4 kv = *(const float4*)(sKt + d * 64 + ((tx ^ (d & 15)) << 2));
#pragma unroll
                for (int i = 0; i < 4; i++) {
                    float qv = ((float*)&q4[i])[dd];
                    sv[i][0] = fmaf(qv, kv.x, sv[i][0]);
                    sv[i][1] = fmaf(qv, kv.y, sv[i][1]);
                    sv[i][2] = fmaf(qv, kv.z, sv[i][2]);
                    sv[i][3] = fmaf(qv, kv.w, sv[i][3]);
                }
            }
        }
#pragma unroll
        for (int i = 0; i < 4; i++) {
            int r = ty * 4 + i;
            float vv[4];
#pragma unroll
            for (int j = 0; j < 4; j++) {
                float val = sv[i][j] * scale;
                if (kt == qt && (tx * 4 + j) > r) val = -3e38f;
                vv[j] = val;
            }
            *(float4*)(sS + r * 64 + tx * 4) = make_float4(vv[0], vv[1], vv[2], vv[3]);
        }
        __syncthreads();

        {
            int w = t >> 5, lane = t & 31;
            for (int rr = 0; rr < 8; rr++) {
                int r = w * 8 + rr;
                float v0 = sS[r * 64 + lane];
                float v1 = sS[r * 64 + lane + 32];
                float mx = fmaxf(v0, v1);
#pragma unroll
                for (int o = 16; o > 0; o >>= 1) mx = fmaxf(mx, __shfl_xor_sync(0xffffffffu, mx, o));
                float mold = sM[r];
                float mnew = fmaxf(mold, mx);
                float p0 = __expf(v0 - mnew);
                float p1 = __expf(v1 - mnew);
                float psum = p0 + p1;
#pragma unroll
                for (int o = 16; o > 0; o >>= 1) psum += __shfl_xor_sync(0xffffffffu, psum, o);
                sS[r * 64 + lane] = p0;
                sS[r * 64 + lane + 32] = p1;
                if (lane == 0) {
                    float corr = __expf(mold - mnew);
                    sC[r] = corr;
                    sL[r] = sL[r] * corr + psum;
                    sM[r] = mnew;
                }
            }
        }
        __syncthreads();

        float corr_i[4];
#pragma unroll
        for (int i = 0; i < 4; i++) corr_i[i] = sC[ty * 4 + i];
#pragma unroll
        for (int i = 0; i < 4; i++)
#pragma unroll
            for (int j = 0; j < 8; j++) acc[i][j] *= corr_i[i];

        for (int n = 0; n < 64; n += 4) {
            float4 p4[4];
#pragma unroll
            for (int i = 0; i < 4; i++)
                p4[i] = *(const float4*)(sS + (ty * 4 + i) * 64 + n);
#pragma unroll
            for (int nn = 0; nn < 4; nn++) {
                float4 va = *(const float4*)(sV + (n + nn) * 128 + tx * 8);
                float4 vb = *(const float4*)(sV + (n + nn) * 128 + tx * 8 + 4);
#pragma unroll
                for (int i = 0; i < 4; i++) {
                    float p = ((float*)&p4[i])[nn];
                    acc[i][0] = fmaf(p, va.x, acc[i][0]);
                    acc[i][1] = fmaf(p, va.y, acc[i][1]);
                    acc[i][2] = fmaf(p, va.z, acc[i][2]);
                    acc[i][3] = fmaf(p, va.w, acc[i][3]);
                    acc[i][4] = fmaf(p, vb.x, acc[i][4]);
                    acc[i][5] = fmaf(p, vb.y, acc[i][5]);
                    acc[i][6] = fmaf(p, vb.z, acc[i][6]);
                    acc[i][7] = fmaf(p, vb.w, acc[i][7]);
                }
            }
        }
    }
    __syncthreads();

    __nv_bfloat16* goh = g_attn_hi  + (size_t)q0 * Q_SIZE + h * HD;
    __nv_bfloat16* gom = g_attn_mid + (size_t)q0 * Q_SIZE + h * HD;
#pragma unroll
    for (int i = 0; i < 4; i++) {
        int r = ty * 4 + i;
        float linv = 1.0f / sL[r];
        float f[8];
#pragma unroll
        for (int j = 0; j < 8; j++) f[j] = acc[i][j] * linv;
        __nv_bfloat16* oh = goh + (size_t)r * Q_SIZE + tx * 8;
        __nv_bfloat16* om = gom + (size_t)r * Q_SIZE + tx * 8;
#pragma unroll
        for (int j = 0; j < 8; j += 2) {
            __nv_bfloat16 h0 = __float2bfloat16(f[j]);
            __nv_bfloat16 h1 = __float2bfloat16(f[j+1]);
            __nv_bfloat162 hp; hp.x = h0; hp.y = h1;
            __nv_bfloat162 mp;
            mp.x = __float2bfloat16(f[j]   - __bfloat162float(h0));
            mp.y = __float2bfloat16(f[j+1] - __bfloat162float(h1));
            *(__nv_bfloat162*)(oh + j) = hp;
            *(__nv_bfloat162*)(om + j) = mp;
        }
    }
}

// ---------------------------------------------------------------------------
extern "C" void kernel_launch(void* const* d_in, const int* in_sizes, int n_in,
                              void* d_out, int out_size) {
    const int*   positions = (const int*)d_in[0];
    const float* hidden    = (const float*)d_in[1];
    const float* lnw       = (const float*)d_in[2];
    const float* w_qkv     = (const float*)d_in[3];
    const float* w_o       = (const float*)d_in[4];
    float* out = (float*)d_out;

    void* p;
    cudaGetSymbolAddress(&p, g_qkv);      float* qkv = (float*)p;
    cudaGetSymbolAddress(&p, g_xn_hi);    __nv_bfloat16* xnh = (__nv_bfloat16*)p;
    cudaGetSymbolAddress(&p, g_xn_mid);   __nv_bfloat16* xnm = (__nv_bfloat16*)p;
    cudaGetSymbolAddress(&p, g_wqkv_hi);  __nv_bfloat16* wqh = (__nv_bfloat16*)p;
    cudaGetSymbolAddress(&p, g_wqkv_mid); __nv_bfloat16* wqm = (__nv_bfloat16*)p;
    cudaGetSymbolAddress(&p, g_wo_hi);    __nv_bfloat16* woh = (__nv_bfloat16*)p;
    cudaGetSymbolAddress(&p, g_wo_mid);   __nv_bfloat16* wom = (__nv_bfloat16*)p;
    cudaGetSymbolAddress(&p, g_attn_hi);  __nv_bfloat16* ath = (__nv_bfloat16*)p;
    cudaGetSymbolAddress(&p, g_attn_mid); __nv_bfloat16* atm = (__nv_bfloat16*)p;

    int flash_smem = (64 * 128 + 128 * 64 + 64 * 128 + 64 * 64 + 3 * 64) * sizeof(float);
    cudaFuncSetAttribute(gemm_mma_kernel, cudaFuncAttributeMaxDynamicSharedMemorySize, GEMM_SMEM);
    cudaFuncSetAttribute(flash_kernel, cudaFuncAttributeMaxDynamicSharedMemorySize, flash_smem);

    // split weights to bf16 hi/mid
    split_kernel<<<(QKV_N * HID / 4 + 255) / 256, 256>>>(w_qkv, wqh, wqm, QKV_N * HID / 4);
    split_kernel<<<(Q_SIZE * HID / 4 + 255) / 256, 256>>>(w_o, woh, wom, Q_SIZE * HID / 4);

    // 1. RMSNorm -> xn hi/mid
    rmsnorm_kernel<<<S_LEN, 256>>>(hidden, lnw);

    // 2. QKV = xn @ w_qkv^T (HMMA split) -> fp32 g_qkv
    {
        dim3 grid(QKV_N / 128, S_LEN / 128);
        gemm_mma_kernel<<<grid, 256, GEMM_SMEM>>>(xnh, xnm, wqh, wqm, qkv, HID, QKV_N);
    }

    // 3. RoPE
    {
        dim3 grid(S_LEN, NQH + NKVH);
        rope_kernel<<<grid, 64>>>(positions);
    }

    // 4. Flash attention -> attn hi/mid
    {
        dim3 grid(S_LEN / 64, NQH);
        flash_kernel<<<grid, 256, flash_smem>>>();
    }

    // 5. out = attn @ w_o^T (HMMA split) -> d_out fp32
    {
        dim3 grid(Q_SIZE / 128, S_LEN / 128);
        gemm_mma_kernel<<<grid, 256, GEMM_SMEM>>>(ath, atm, woh, wom, out, HID, Q_SIZE);
    }
    (void)in_sizes; (void)n_in; (void)out_size;
}

// round 11
// speedup vs baseline: 3.0583x; 1.6461x over previous
#include <cuda_runtime.h>
#include <cuda_bf16.h>
#include <math.h>
#include <stdint.h>

#define S_LEN 2048
#define HID   4096
#define NQH   32
#define NKVH  8
#define HD    128
#define QKV_N 6144
#define KV_OFF 4096
#define V_OFF  5120
#define Q_SIZE 4096

// ---------------- scratch (device globals, allocation-free) ----------------
__device__ float         g_qkv[S_LEN * QKV_N];
__device__ __nv_bfloat16 g_xn_hi[S_LEN * HID];
__device__ __nv_bfloat16 g_xn_mid[S_LEN * HID];
__device__ __nv_bfloat16 g_wqkv_hi[QKV_N * HID];
__device__ __nv_bfloat16 g_wqkv_mid[QKV_N * HID];
__device__ __nv_bfloat16 g_wo_hi[Q_SIZE * HID];
__device__ __nv_bfloat16 g_wo_mid[Q_SIZE * HID];
__device__ __nv_bfloat16 g_attn_hi[S_LEN * Q_SIZE];
__device__ __nv_bfloat16 g_attn_mid[S_LEN * Q_SIZE];

// ---------------- helpers ----------------
__device__ __forceinline__ uint32_t smem_u32(const void* p) {
    uint32_t a;
    asm("{ .reg .u64 t; cvta.to.shared.u64 t, %1; cvt.u32.u64 %0, t; }" : "=r"(a) : "l"(p));
    return a;
}
__device__ __forceinline__ void cp_async16(uint32_t dst, const void* src) {
    asm volatile("cp.async.cg.shared.global [%0], [%1], 16;" :: "r"(dst), "l"(src) : "memory");
}
__device__ __forceinline__ void cp_commit() { asm volatile("cp.async.commit_group;" ::: "memory"); }
__device__ __forceinline__ void cp_wait1() { asm volatile("cp.async.wait_group 1;" ::: "memory"); }
__device__ __forceinline__ void cp_wait0() { asm volatile("cp.async.wait_group 0;" ::: "memory"); }

#define LDSM4(r, addr)                                                             \
    asm volatile("ldmatrix.sync.aligned.m8n8.x4.shared.b16 {%0,%1,%2,%3}, [%4];"   \
        : "=r"((r)[0]), "=r"((r)[1]), "=r"((r)[2]), "=r"((r)[3]) : "r"(addr))

#define LDSM4T(r, addr)                                                                 \
    asm volatile("ldmatrix.sync.aligned.m8n8.x4.trans.shared.b16 {%0,%1,%2,%3}, [%4];"  \
        : "=r"((r)[0]), "=r"((r)[1]), "=r"((r)[2]), "=r"((r)[3]) : "r"(addr))

#define MMA16816(d, a, b0, b1)                                                     \
    asm volatile("mma.sync.aligned.m16n8k16.row.col.f32.bf16.bf16.f32 "            \
        "{%0,%1,%2,%3}, {%4,%5,%6,%7}, {%8,%9}, {%0,%1,%2,%3};"                    \
        : "+f"((d)[0]), "+f"((d)[1]), "+f"((d)[2]), "+f"((d)[3])                   \
        : "r"((a)[0]), "r"((a)[1]), "r"((a)[2]), "r"((a)[3]), "r"(b0), "r"(b1))

__device__ __forceinline__ void split2(float a, float b, uint32_t& hi, uint32_t& mid) {
    __nv_bfloat16 ha = __float2bfloat16(a), hb = __float2bfloat16(b);
    __nv_bfloat16 ma = __float2bfloat16(a - __bfloat162float(ha));
    __nv_bfloat16 mb = __float2bfloat16(b - __bfloat162float(hb));
    __nv_bfloat162 hv; hv.x = ha; hv.y = hb;
    __nv_bfloat162 mv; mv.x = ma; mv.y = mb;
    hi = *(uint32_t*)&hv; mid = *(uint32_t*)&mv;
}

// ---------------------------------------------------------------------------
// RMSNorm -> split bf16 (hi, mid)
// ---------------------------------------------------------------------------
__global__ __launch_bounds__(256) void rmsnorm_kernel(const float* __restrict__ x,
                                                      const float* __restrict__ w) {
    int row = blockIdx.x;
    int t = threadIdx.x;
    const float4* xr = (const float4*)(x + (size_t)row * HID);
    float4 v[4];
    float ss = 0.f;
#pragma unroll
    for (int i = 0; i < 4; i++) {
        v[i] = xr[t + i * 256];
        ss += v[i].x * v[i].x + v[i].y * v[i].y + v[i].z * v[i].z + v[i].w * v[i].w;
    }
    __shared__ float red[8];
#pragma unroll
    for (int o = 16; o > 0; o >>= 1) ss += __shfl_xor_sync(0xffffffffu, ss, o);
    if ((t & 31) == 0) red[t >> 5] = ss;
    __syncthreads();
    if (t < 8) {
        float s2 = red[t];
#pragma unroll
        for (int o = 4; o > 0; o >>= 1) s2 += __shfl_xor_sync(0xffu, s2, o);
        if (t == 0) red[0] = s2;
    }
    __syncthreads();
    float inv = rsqrtf(red[0] / (float)HID + 1e-5f);
    const float4* wr = (const float4*)w;
    __nv_bfloat16* oh = g_xn_hi + (size_t)row * HID;
    __nv_bfloat16* om = g_xn_mid + (size_t)row * HID;
#pragma unroll
    for (int i = 0; i < 4; i++) {
        float4 wv = wr[t + i * 256];
        float f[4];
        f[0] = v[i].x * inv * wv.x; f[1] = v[i].y * inv * wv.y;
        f[2] = v[i].z * inv * wv.z; f[3] = v[i].w * inv * wv.w;
        int base = (t + i * 256) * 4;
        uint32_t h0, m0, h1, m1;
        split2(f[0], f[1], h0, m0);
        split2(f[2], f[3], h1, m1);
        *(uint32_t*)(oh + base)     = h0;
        *(uint32_t*)(oh + base + 2) = h1;
        *(uint32_t*)(om + base)     = m0;
        *(uint32_t*)(om + base + 2) = m1;
    }
}

// ---------------------------------------------------------------------------
// fp32 -> (hi, mid) bf16 split
// ---------------------------------------------------------------------------
__global__ __launch_bounds__(256) void split_kernel(const float* __restrict__ s,
                                                    __nv_bfloat16* __restrict__ hi,
                                                    __nv_bfloat16* __restrict__ mid, int n4) {
    int i = blockIdx.x * 256 + threadIdx.x;
    if (i >= n4) return;
    float4 v = ((const float4*)s)[i];
    uint32_t h0, m0, h1, m1;
    split2(v.x, v.y, h0, m0);
    split2(v.z, v.w, h1, m1);
    *(uint32_t*)(hi + i*4)      = h0;
    *(uint32_t*)(hi + i*4 + 2)  = h1;
    *(uint32_t*)(mid + i*4)     = m0;
    *(uint32_t*)(mid + i*4 + 2) = m1;
}

// ---------------------------------------------------------------------------
// mma.sync bf16-split GEMM:  C[m][n] = sum_k A[m][k]*B[n][k]
// 128x128 tile, BK=32, 8 warps (4x2), 2-stage cp.async, stride-80 smem.
// ---------------------------------------------------------------------------
#define GK   32
#define TSTR 80
#define TILE_B (128 * TSTR)
#define STAGE_B (4 * TILE_B)
#define GEMM_SMEM (2 * STAGE_B)

__global__ __launch_bounds__(256) void gemm_mma_kernel(
    const __nv_bfloat16* __restrict__ Ah, const __nv_bfloat16* __restrict__ Am,
    const __nv_bfloat16* __restrict__ Bh, const __nv_bfloat16* __restrict__ Bm,
    float* __restrict__ C, int K, int N)
{
    extern __shared__ char smem[];
    int t = threadIdx.x;
    int lane = t & 31, warp = t >> 5;
    int wm = warp & 3, wn = warp >> 2;
    int m0 = blockIdx.y * 128, n0 = blockIdx.x * 128;

    const __nv_bfloat16* gsrc[4] = { Ah + (size_t)m0 * K, Am + (size_t)m0 * K,
                                     Bh + (size_t)n0 * K, Bm + (size_t)n0 * K };
    uint32_t sbase = smem_u32(smem);
    int lr = t >> 2, lseg = t & 3;

    float acc[2][8][4];
#pragma unroll
    for (int i = 0; i < 2; i++)
#pragma unroll
        for (int j = 0; j < 8; j++)
#pragma unroll
            for (int q = 0; q < 4; q++) acc[i][j][q] = 0.f;

    int NC = K / GK;
    {
#pragma unroll
        for (int mt = 0; mt < 4; mt++) {
            const __nv_bfloat16* g = gsrc[mt] + (size_t)lr * K + lseg * 8;
            uint32_t d = sbase + mt * TILE_B + lr * TSTR + lseg * 16;
            cp_async16(d, g);
            cp_async16(d + 64 * TSTR, g + (size_t)64 * K);
        }
        cp_commit();
    }

    for (int c = 0; c < NC; c++) {
        int s = c & 1;
        if (c + 1 < NC) {
            int kc = (c + 1) * GK;
#pragma unroll
            for (int mt = 0; mt < 4; mt++) {
                const __nv_bfloat16* g = gsrc[mt] + (size_t)lr * K + kc + lseg * 8;
                uint32_t d = sbase + (s ^ 1) * STAGE_B + mt * TILE_B + lr * TSTR + lseg * 16;
                cp_async16(d, g);
                cp_async16(d + 64 * TSTR, g + (size_t)64 * K);
            }
            cp_commit();
            cp_wait1();
        } else {
            cp_wait0();
        }
        __syncthreads();

        uint32_t st = sbase + s * STAGE_B;
#pragma unroll
        for (int kk = 0; kk < 2; kk++) {
            uint32_t a_hi[2][4], a_mi[2][4];
            int kbA = kk * 32 + ((lane >> 4) << 4);
#pragma unroll
            for (int mf = 0; mf < 2; mf++) {
                uint32_t addr = st + (uint32_t)(wm * 32 + mf * 16 + (lane & 15)) * TSTR + kbA;
                LDSM4(a_hi[mf], addr);
                LDSM4(a_mi[mf], addr + TILE_B);
            }
            uint32_t b_hi[4][4], b_mi[4][4];
            int q = lane >> 3;
            int nbase = wn * 64 + ((q & 2) << 2) + (lane & 7);
            int kbB = kk * 32 + ((q & 1) << 4);
#pragma unroll
            for (int g = 0; g < 4; g++) {
                uint32_t addr = st + 2 * TILE_B + (uint32_t)(nbase + g * 16) * TSTR + kbB;
                LDSM4(b_hi[g], addr);
                LDSM4(b_mi[g], addr + TILE_B);
            }
#pragma unroll
            for (int mf = 0; mf < 2; mf++) {
#pragma unroll
                for (int nf = 0; nf < 8; nf++) {
                    int g = nf >> 1, j = (nf & 1) * 2;
                    MMA16816(acc[mf][nf], a_hi[mf], b_hi[g][j], b_hi[g][j + 1]);
                    MMA16816(acc[mf][nf], a_hi[mf], b_mi[g][j], b_mi[g][j + 1]);
                    MMA16816(acc[mf][nf], a_mi[mf], b_hi[g][j], b_hi[g][j + 1]);
                }
            }
        }
        __syncthreads();
    }

#pragma unroll
    for (int mf = 0; mf < 2; mf++) {
#pragma unroll
        for (int nf = 0; nf < 8; nf++) {
            int r = m0 + wm * 32 + mf * 16 + (lane >> 2);
            int cc = n0 + wn * 64 + nf * 8 + (lane & 3) * 2;
            *(float2*)&C[(size_t)r * N + cc]       = make_float2(acc[mf][nf][0], acc[mf][nf][1]);
            *(float2*)&C[(size_t)(r + 8) * N + cc] = make_float2(acc[mf][nf][2], acc[mf][nf][3]);
        }
    }
}

// ---------------------------------------------------------------------------
// RoPE in-place on Q/K in g_qkv (fp32)
// ---------------------------------------------------------------------------
__global__ __launch_bounds__(64) void rope_kernel(const int* __restrict__ positions) {
    int s = blockIdx.x;
    int h = blockIdx.y;
    int d = threadIdx.x;
    float pos = (float)positions[s];
    float invf = powf(10000.0f, -((float)(2 * d)) / 128.0f);
    float f = pos * invf;
    float c = cosf(f), sn = sinf(f);
    float* base;
    if (h < NQH) base = g_qkv + (size_t)s * QKV_N + h * HD;
    else         base = g_qkv + (size_t)s * QKV_N + KV_OFF + (h - NQH) * HD;
    float x1 = base[d];
    float x2 = base[d + 64];
    base[d]      = x1 * c - x2 * sn;
    base[d + 64] = x2 * c + x1 * sn;
}

// ---------------------------------------------------------------------------
// Tensorized flash attention (causal, GQA 4:1), bf16 hi/mid split HMMA.
// CTA: 128 q-rows x 1 head. 8 warps, each m16 x n64 per kv tile of 64.
// ---------------------------------------------------------------------------
#define FSTR 272
#define FQ_B  (128 * FSTR)   // 34816
#define FK_B  (64 * FSTR)    // 17408
#define FLASH_SMEM (2 * FQ_B + 4 * FK_B)   // 139264

__global__ __launch_bounds__(256) void flash_mma_kernel() {
    extern __shared__ char fsm[];
    char* sQh = fsm;
    char* sKh = fsm + 2 * FQ_B;
    char* sVh = fsm + 2 * FQ_B + 2 * FK_B;

    int qt = 15 - (int)blockIdx.x;        // heavy tiles first
    int h  = blockIdx.y;
    int kvh = h >> 2;
    int t = threadIdx.x;
    int lane = t & 31, wid = t >> 5;
    int q0 = qt * 128;
    const float scale = 0.08838834764831845f;

    uint32_t uQh = smem_u32(sQh);
    uint32_t uKh = smem_u32(sKh);
    uint32_t uVh = smem_u32(sVh);

    // load Q tile (128 rows x 32 float4-chunks = 4096 -> 16 iters), fold scale, split hi/mid
    {
        const float* gq = g_qkv + (size_t)q0 * QKV_N + h * HD;
#pragma unroll
        for (int i = 0; i < 16; i++) {
            int idx = t + i * 256;
            int r = idx >> 5, c4 = idx & 31;
            float4 v = *(const float4*)(gq + (size_t)r * QKV_N + c4 * 4);
            uint32_t h0, m0, h1, m1;
            split2(v.x * scale, v.y * scale, h0, m0);
            split2(v.z * scale, v.w * scale, h1, m1);
            uint32_t off = (uint32_t)r * FSTR + c4 * 8;
            *(uint2*)(sQh + off)        = make_uint2(h0, h1);
            *(uint2*)(sQh + FQ_B + off) = make_uint2(m0, m1);
        }
    }

    float rm0 = -1e30f, rm1 = -1e30f, rl0 = 0.f, rl1 = 0.f;
    float o[16][4];
#pragma unroll
    for (int i = 0; i < 16; i++)
#pragma unroll
        for (int j = 0; j < 4; j++) o[i][j] = 0.f;

    int ktmax = 2 * qt + 1;
    for (int kt = 0; kt <= ktmax; kt++) {
        int n0 = kt * 64;
        __syncthreads();
        const float* gk = g_qkv + (size_t)n0 * QKV_N + KV_OFF + kvh * HD;
        const float* gv = g_qkv + (size_t)n0 * QKV_N + V_OFF + kvh * HD;
#pragma unroll
        for (int i = 0; i < 8; i++) {
            int idx = t + i * 256;       // 2048 = 64 rows x 32 float4-chunks
            int r = idx >> 5, c4 = idx & 31;
            uint32_t off = (uint32_t)r * FSTR + c4 * 8;
            float4 kv4 = *(const float4*)(gk + (size_t)r * QKV_N + c4 * 4);
            uint32_t h0, m0, h1, m1;
            split2(kv4.x, kv4.y, h0, m0);
            split2(kv4.z, kv4.w, h1, m1);
            *(uint2*)(sKh + off)        = make_uint2(h0, h1);
            *(uint2*)(sKh + FK_B + off) = make_uint2(m0, m1);
            float4 vv4 = *(const float4*)(gv + (size_t)r * QKV_N + c4 * 4);
            split2(vv4.x, vv4.y, h0, m0);
            split2(vv4.z, vv4.w, h1, m1);
            *(uint2*)(sVh + off)        = make_uint2(h0, h1);
            *(uint2*)(sVh + FK_B + off) = make_uint2(m0, m1);
        }
        __syncthreads();

        // S = Q K^T  (warp: m16 x n64)
        float s[8][4];
#pragma unroll
        for (int i = 0; i < 8; i++)
#pragma unroll
            for (int j = 0; j < 4; j++) s[i][j] = 0.f;

        int q = lane >> 3;
        uint32_t brow = ((q & 2) << 2) + (lane & 7);
        uint32_t bko  = (uint32_t)((q & 1) << 4);
#pragma unroll
        for (int kc = 0; kc < 8; kc++) {
            uint32_t ah[4], am[4];
            uint32_t aaddr = uQh + (uint32_t)(wid * 16 + (lane & 15)) * FSTR + kc * 32 + ((lane >> 4) << 4);
            LDSM4(ah, aaddr);
            LDSM4(am, aaddr + FQ_B);
#pragma unroll
            for (int g = 0; g < 4; g++) {
                uint32_t bh[4], bm[4];
                uint32_t baddr = uKh + (uint32_t)(g * 16 + brow) * FSTR + kc * 32 + bko;
                LDSM4(bh, baddr);
                LDSM4(bm, baddr + FK_B);
                MMA16816(s[2*g],   ah, bh[0], bh[1]);
                MMA16816(s[2*g],   ah, bm[0], bm[1]);
                MMA16816(s[2*g],   am, bh[0], bh[1]);
                MMA16816(s[2*g+1], ah, bh[2], bh[3]);
                MMA16816(s[2*g+1], ah, bm[2], bm[3]);
                MMA16816(s[2*g+1], am, bh[2], bh[3]);
            }
        }

        int r0g = q0 + wid * 16 + (lane >> 2);
        if (kt >= 2 * qt) {
#pragma unroll
            for (int nf = 0; nf < 8; nf++) {
                int c0 = n0 + nf * 8 + (lane & 3) * 2;
                if (c0     > r0g)     s[nf][0] = -1e30f;
                if (c0 + 1 > r0g)     s[nf][1] = -1e30f;
                if (c0     > r0g + 8) s[nf][2] = -1e30f;
                if (c0 + 1 > r0g + 8) s[nf][3] = -1e30f;
            }
        }
        float mx0 = -1e30f, mx1 = -1e30f;
#pragma unroll
        for (int nf = 0; nf < 8; nf++) {
            mx0 = fmaxf(mx0, fmaxf(s[nf][0], s[nf][1]));
            mx1 = fmaxf(mx1, fmaxf(s[nf][2], s[nf][3]));
        }
        mx0 = fmaxf(mx0, __shfl_xor_sync(0xffffffffu, mx0, 1));
        mx0 = fmaxf(mx0, __shfl_xor_sync(0xffffffffu, mx0, 2));
        mx1 = fmaxf(mx1, __shfl_xor_sync(0xffffffffu, mx1, 1));
        mx1 = fmaxf(mx1, __shfl_xor_sync(0xffffffffu, mx1, 2));
        float mn0 = fmaxf(rm0, mx0), mn1 = fmaxf(rm1, mx1);
        float cr0 = __expf(rm0 - mn0), cr1 = __expf(rm1 - mn1);
        rm0 = mn0; rm1 = mn1;

        uint32_t pah[4][4], pam[4][4];
        float ls0 = 0.f, ls1 = 0.f;
#pragma unroll
        for (int g = 0; g < 4; g++) {
            float pA0 = __expf(s[2*g][0]   - mn0), pA1 = __expf(s[2*g][1]   - mn0);
            float pA2 = __expf(s[2*g][2]   - mn1), pA3 = __expf(s[2*g][3]   - mn1);
            float pB0 = __expf(s[2*g+1][0] - mn0), pB1 = __expf(s[2*g+1][1] - mn0);
            float pB2 = __expf(s[2*g+1][2] - mn1), pB3 = __expf(s[2*g+1][3] - mn1);
            ls0 += pA0 + pA1 + pB0 + pB1;
            ls1 += pA2 + pA3 + pB2 + pB3;
            split2(pA0, pA1, pah[g][0], pam[g][0]);
            split2(pA2, pA3, pah[g][1], pam[g][1]);
            split2(pB0, pB1, pah[g][2], pam[g][2]);
            split2(pB2, pB3, pah[g][3], pam[g][3]);
        }
        ls0 += __shfl_xor_sync(0xffffffffu, ls0, 1);
        ls0 += __shfl_xor_sync(0xffffffffu, ls0, 2);
        ls1 += __shfl_xor_sync(0xffffffffu, ls1, 1);
        ls1 += __shfl_xor_sync(0xffffffffu, ls1, 2);
        rl0 = rl0 * cr0 + ls0;
        rl1 = rl1 * cr1 + ls1;

#pragma unroll
        for (int nf = 0; nf < 16; nf++) {
            o[nf][0] *= cr0; o[nf][1] *= cr0;
            o[nf][2] *= cr1; o[nf][3] *= cr1;
        }

        // O += P V   (B frags via ldmatrix.trans on V[kv][d])
#pragma unroll
        for (int g = 0; g < 4; g++) {
#pragma unroll
            for (int dg = 0; dg < 8; dg++) {
                uint32_t bh[4], bm[4];
                uint32_t vaddr = uVh + (uint32_t)(g * 16 + (lane & 15)) * FSTR + dg * 32 + ((lane >> 4) << 4);
                LDSM4T(bh, vaddr);
                LDSM4T(bm, vaddr + FK_B);
                MMA16816(o[2*dg],   pah[g], bh[0], bh[1]);
                MMA16816(o[2*dg],   pah[g], bm[0], bm[1]);
                MMA16816(o[2*dg],   pam[g], bh[0], bh[1]);
                MMA16816(o[2*dg+1], pah[g], bh[2], bh[3]);
                MMA16816(o[2*dg+1], pah[g], bm[2], bm[3]);
                MMA16816(o[2*dg+1], pam[g], bh[2], bh[3]);
            }
        }
    }

    // epilogue: normalize, split hi/mid, store
    float li0 = 1.f / rl0, li1 = 1.f / rl1;
    int r = q0 + wid * 16 + (lane >> 2);
    __nv_bfloat16* goh = g_attn_hi  + (size_t)r * Q_SIZE + h * HD + (lane & 3) * 2;
    __nv_bfloat16* gom = g_attn_mid + (size_t)r * Q_SIZE + h * HD + (lane & 3) * 2;
#pragma unroll
    for (int nf = 0; nf < 16; nf++) {
        uint32_t h0, m0, h1, m1;
        split2(o[nf][0] * li0, o[nf][1] * li0, h0, m0);
        split2(o[nf][2] * li1, o[nf][3] * li1, h1, m1);
        *(uint32_t*)(goh + nf * 8)                      = h0;
        *(uint32_t*)(gom + nf * 8)                      = m0;
        *(uint32_t*)(goh + (size_t)8 * Q_SIZE + nf * 8) = h1;
        *(uint32_t*)(gom + (size_t)8 * Q_SIZE + nf * 8) = m1;
    }
}

// ---------------------------------------------------------------------------
extern "C" void kernel_launch(void* const* d_in, const int* in_sizes, int n_in,
                              void* d_out, int out_size) {
    const int*   positions = (const int*)d_in[0];
    const float* hidden    = (const float*)d_in[1];
    const float* lnw       = (const float*)d_in[2];
    const float* w_qkv     = (const float*)d_in[3];
    const float* w_o       = (const float*)d_in[4];
    float* out = (float*)d_out;

    void* p;
    cudaGetSymbolAddress(&p, g_qkv);      float* qkv = (float*)p;
    cudaGetSymbolAddress(&p, g_xn_hi);    __nv_bfloat16* xnh = (__nv_bfloat16*)p;
    cudaGetSymbolAddress(&p, g_xn_mid);   __nv_bfloat16* xnm = (__nv_bfloat16*)p;
    cudaGetSymbolAddress(&p, g_wqkv_hi);  __nv_bfloat16* wqh = (__nv_bfloat16*)p;
    cudaGetSymbolAddress(&p, g_wqkv_mid); __nv_bfloat16* wqm = (__nv_bfloat16*)p;
    cudaGetSymbolAddress(&p, g_wo_hi);    __nv_bfloat16* woh = (__nv_bfloat16*)p;
    cudaGetSymbolAddress(&p, g_wo_mid);   __nv_bfloat16* wom = (__nv_bfloat16*)p;
    cudaGetSymbolAddress(&p, g_attn_hi);  __nv_bfloat16* ath = (__nv_bfloat16*)p;
    cudaGetSymbolAddress(&p, g_attn_mid); __nv_bfloat16* atm = (__nv_bfloat16*)p;

    cudaFuncSetAttribute(gemm_mma_kernel, cudaFuncAttributeMaxDynamicSharedMemorySize, GEMM_SMEM);
    cudaFuncSetAttribute(flash_mma_kernel, cudaFuncAttributeMaxDynamicSharedMemorySize, FLASH_SMEM);

    // split weights to bf16 hi/mid
    split_kernel<<<(QKV_N * HID / 4 + 255) / 256, 256>>>(w_qkv, wqh, wqm, QKV_N * HID / 4);
    split_kernel<<<(Q_SIZE * HID / 4 + 255) / 256, 256>>>(w_o, woh, wom, Q_SIZE * HID / 4);

    // 1. RMSNorm -> xn hi/mid
    rmsnorm_kernel<<<S_LEN, 256>>>(hidden, lnw);

    // 2. QKV = xn @ w_qkv^T (HMMA split) -> fp32 g_qkv
    {
        dim3 grid(QKV_N / 128, S_LEN / 128);
        gemm_mma_kernel<<<grid, 256, GEMM_SMEM>>>(xnh, xnm, wqh, wqm, qkv, HID, QKV_N);
    }

    // 3. RoPE
    {
        dim3 grid(S_LEN, NQH + NKVH);
        rope_kernel<<<grid, 64>>>(positions);
    }

    // 4. Tensorized flash attention -> attn hi/mid
    {
        dim3 grid(S_LEN / 128, NQH);
        flash_mma_kernel<<<grid, 256, FLASH_SMEM>>>();
    }

    // 5. out = attn @ w_o^T (HMMA split) -> d_out fp32
    {
        dim3 grid(Q_SIZE / 128, S_LEN / 128);
        gemm_mma_kernel<<<grid, 256, GEMM_SMEM>>>(ath, atm, woh, wom, out, HID, Q_SIZE);
    }
    (void)in_sizes; (void)n_in; (void)out_size;
}